// round 13
// baseline (speedup 1.0000x reference)
#include <cuda_runtime.h>
#include <math.h>

// Problem shape (fixed by reference setup_inputs)
#define UU 2048
#define TT 512
#define QQ 10000
#define HH 128
#define UT (UU*TT)
#define CH 16          // scan: time steps per lane (32 lanes * 16 = 512)

#define TBLK 592       // table kernel blocks (4/SM)
#define NCHUNK 1250    // 16-pair chunks: 1250*16 = 20000 exactly

// Scratch (device globals: allocation-free, graph-capturable)
__device__ float  g_diff[QQ];
__device__ float  g_disc[QQ];
__device__ float2 g_tab[2*QQ];     // (mu, lmda) per (q, resp)

__device__ __forceinline__ float gelu_exact(float x) {
    return 0.5f * x * (1.0f + erff(x * 0.70710678118654752440f));
}

// ---------------------------------------------------------------------------
// Kernel 1 (fused sample + MLP table): resp = round(uniform) in {0,1}, so the
// MLP has only 2*QQ distinct inputs. 256 threads/block, two 128-thread halves,
// each half computes 8 pairs (4 q x 2 resp) per W2 pass (73% FFMA issue mix).
// Grid-strided over exactly NCHUNK chunks; 4 blocks/SM for latency hiding.
// ---------------------------------------------------------------------------
__global__ void __launch_bounds__(256) table_kernel(
        const float* __restrict__ dmu, const float* __restrict__ dlv,
        const float* __restrict__ cmu, const float* __restrict__ clv,
        const float* __restrict__ ed,  const float* __restrict__ ec,
        const float* __restrict__ W1, const float* __restrict__ b1,
        const float* __restrict__ W2, const float* __restrict__ b2,
        const float* __restrict__ W3, const float* __restrict__ b3) {
    const int tid  = threadIdx.x;
    const int half = tid >> 7;          // 0 or 1
    const int j    = tid & 127;         // channel
    const int wwarp = (tid >> 5) & 3;   // warp within half
    const int lane  = tid & 31;

    // ---- folded sample pass (first 40 blocks cover QQ) ----
    int gid = blockIdx.x * 256 + tid;
    if (gid < QQ) {
        g_diff[gid] = fmaf(__expf(0.5f * dlv[gid]), ed[gid], dmu[gid]);
        g_disc[gid] = fmaf(__expf(0.5f * clv[gid]), ec[gid], cmu[gid]);
    }

    __shared__ __align__(16) float h1s[16][HH];   // 16 pairs per chunk
    __shared__ float s_red[16][2][4];             // [pair][comp][warp]

    const float w1a = __ldg(&W1[j]);
    const float w1b = __ldg(&W1[HH + j]);
    const float w1c = __ldg(&W1[2*HH + j]);
    const float b1j = __ldg(&b1[j]);
    const float b2j = __ldg(&b2[j]);
    const float w3a = __ldg(&W3[2*j + 0]);
    const float w3b = __ldg(&W3[2*j + 1]);
    const float b30 = __ldg(&b3[0]);
    const float b31 = __ldg(&b3[1]);

    for (int c = blockIdx.x; c < NCHUNK; c += TBLK) {
        const int pbase = c * 16;            // 16 pairs; all < 2*QQ by range
        const int qbase = c * 8 + half * 4;  // this half's 4 q's

        // ---- layer 1: 4 q's x {resp=0,1} -> 8 h rows for this half ----
#pragma unroll
        for (int g = 0; g < 4; ++g) {
            int q = qbase + g;
            float td = fmaf(__expf(0.5f * __ldg(&dlv[q])), __ldg(&ed[q]), __ldg(&dmu[q]));
            float tc = fmaf(__expf(0.5f * __ldg(&clv[q])), __ldg(&ec[q]), __ldg(&cmu[q]));
            float pre0 = fmaf(td, w1a, fmaf(tc, w1b, b1j));   // resp = 0
            float pre1 = pre0 + w1c;                          // resp = 1
            h1s[half*8 + 2*g + 0][j] = gelu_exact(pre0);
            h1s[half*8 + 2*g + 1][j] = gelu_exact(pre1);
        }
        __syncthreads();

        // ---- layer 2: one W2 pass feeds 8 accumulators ----
        float acc[8];
#pragma unroll
        for (int p = 0; p < 8; ++p) acc[p] = b2j;
#pragma unroll 4
        for (int kc = 0; kc < 32; ++kc) {
            int k = kc * 4;
            float w0 = __ldg(&W2[(k+0)*HH + j]);
            float w1 = __ldg(&W2[(k+1)*HH + j]);
            float w2 = __ldg(&W2[(k+2)*HH + j]);
            float w3 = __ldg(&W2[(k+3)*HH + j]);
#pragma unroll
            for (int p = 0; p < 8; ++p) {
                float4 v = *reinterpret_cast<const float4*>(&h1s[half*8 + p][k]);
                acc[p] = fmaf(v.x, w0, fmaf(v.y, w1, fmaf(v.z, w2, fmaf(v.w, w3, acc[p]))));
            }
        }

        // ---- layer 3: 16 values per lane (8 pairs x {m0,m1}) ----
        float val[16];
#pragma unroll
        for (int p = 0; p < 8; ++p) {
            float hv = gelu_exact(acc[p]);
            val[2*p + 0] = hv * w3a;
            val[2*p + 1] = hv * w3b;
        }
        // Multi-value butterfly: stages o=16,8,4,2 halve the value count
        // (keep-half/exchange-half); after them lane L owns value (L>>1)&15;
        // stage o=1 completes the 32-lane sum. 15 shuffles total.
        {
            bool b16 = (lane & 16) != 0;
#pragma unroll
            for (int i = 0; i < 8; ++i) {
                float send = b16 ? val[i] : val[8+i];
                float r = __shfl_xor_sync(0xffffffffu, send, 16);
                val[i] = (b16 ? val[8+i] : val[i]) + r;
            }
            bool b8 = (lane & 8) != 0;
#pragma unroll
            for (int i = 0; i < 4; ++i) {
                float send = b8 ? val[i] : val[4+i];
                float r = __shfl_xor_sync(0xffffffffu, send, 8);
                val[i] = (b8 ? val[4+i] : val[i]) + r;
            }
            bool b4 = (lane & 4) != 0;
#pragma unroll
            for (int i = 0; i < 2; ++i) {
                float send = b4 ? val[i] : val[2+i];
                float r = __shfl_xor_sync(0xffffffffu, send, 4);
                val[i] = (b4 ? val[2+i] : val[i]) + r;
            }
            bool b2v = (lane & 2) != 0;
            {
                float send = b2v ? val[0] : val[1];
                float r = __shfl_xor_sync(0xffffffffu, send, 2);
                val[0] = (b2v ? val[1] : val[0]) + r;
            }
            val[0] += __shfl_xor_sync(0xffffffffu, val[0], 1);
        }
        if ((lane & 1) == 0) {
            int v = (lane >> 1) & 15;       // owned value index: p*2 + comp
            s_red[half*8 + (v >> 1)][v & 1][wwarp] = val[0];
        }
        __syncthreads();

        if (tid < 16) {                     // one thread finalizes each pair
            int pair = pbase + tid;
            float mu = b30 + ((s_red[tid][0][0] + s_red[tid][0][1])
                            + (s_red[tid][0][2] + s_red[tid][0][3]));
            float p1 = b31 + ((s_red[tid][1][0] + s_red[tid][1][1])
                            + (s_red[tid][1][2] + s_red[tid][1][3]));
            g_tab[pair] = make_float2(mu, fminf(__expf(-p1), 1e32f));
        }
        __syncthreads();
    }
}

// ---------------------------------------------------------------------------
// Kernel 2 (fused): per-user backward + forward scans via chunked warp scans.
// One warp per user (4 users / 128-thread block); lane k owns t in [16k,16k+16).
// Register diet vs R12: mask is sign-encoded into l (masked-out => l = -1);
// eps is reloaded in the replay loop, q_id in the output loop (L1 hits).
// Peak live arrays: l/lm then inv/bet (64 regs) + 7 scan state.
// ---------------------------------------------------------------------------
__global__ void __launch_bounds__(128, 6) fused_scan_kernel(
        const int*   __restrict__ mask,
        const int*   __restrict__ q_id,
        const float* __restrict__ resp,
        const float* __restrict__ eps_ab,
        float*       __restrict__ out) {
    const int u = blockIdx.x * 4 + (threadIdx.x >> 5);
    const int k = threadIdx.x & 31;
    const int base = u * TT + k * CH;

    // ---- preprocess 16 trials -> l (sign-encoded mask), lm ----
    float l[CH], lm[CH];
#pragma unroll
    for (int v = 0; v < 4; ++v) {
        int4   mk = reinterpret_cast<const int4*>(mask + base)[v];
        int4   q  = reinterpret_cast<const int4*>(q_id + base)[v];
        float4 r  = reinterpret_cast<const float4*>(resp + base)[v];
        int   mkv[4] = {mk.x, mk.y, mk.z, mk.w};
        int   qv[4]  = {q.x, q.y, q.z, q.w};
        float rv[4]  = {r.x, r.y, r.z, r.w};
#pragma unroll
        for (int s = 0; s < 4; ++s) {
            int i = v*4 + s;
            float2 ml = g_tab[(qv[s] << 1) | (rv[s] > 0.5f ? 1 : 0)];
            bool m = (mkv[s] != 0);
            l[i]  = m ? ml.y : -1.0f;     // l >= 0 always when unmasked
            lm[i] = ml.y * ml.x;          // unused when masked
        }
    }

    // ---- backward: per-lane chunk matrix ----
    float A11 = 1.f, A12 = 0.f, A21 = 0.f, A22 = 1.f;
    float C1 = 0.f, C2 = 0.f, WC = 1.f;
#pragma unroll
    for (int i = CH - 1; i >= 0; --i) {
        if (l[i] >= 0.f) {
            float li = l[i];
            float s  = __fdividef(1.0f, 1.0f + li);
            float n11 = (A11 + li * A21) * s;
            float n12 = (A12 + li * A22) * s;
            float n21 = n11 + A21 * s;
            float n22 = n12 + A22 * s;
            float nc1 = fmaf(lm[i], A21, C1) * s;
            float nc2 = fmaf(lm[i], A22, C2) * s;
            A11 = n11; A12 = n12; A21 = n21; A22 = n22;
            C1 = nc1; C2 = nc2; WC *= s;
        }
    }
    {
        float s = __fdividef(1.0f, A22);
        A11 *= s; A12 *= s; A21 *= s; A22 *= s;
        C1 *= s; C2 *= s; WC *= s;
    }

    // ---- warp suffix scan (Z = A*Y; w-row: zc = C*y + WC*yc) ----
#pragma unroll
    for (int off = 1; off < 32; off <<= 1) {
        float y11 = __shfl_down_sync(0xffffffffu, A11, off);
        float y12 = __shfl_down_sync(0xffffffffu, A12, off);
        float y21 = __shfl_down_sync(0xffffffffu, A21, off);
        float y22 = __shfl_down_sync(0xffffffffu, A22, off);
        float yc1 = __shfl_down_sync(0xffffffffu, C1,  off);
        float yc2 = __shfl_down_sync(0xffffffffu, C2,  off);
        float ywc = __shfl_down_sync(0xffffffffu, WC,  off);
        if (k + off < 32) {
            float z11 = fmaf(A11, y11, A12 * y21);
            float z12 = fmaf(A11, y12, A12 * y22);
            float z21 = fmaf(A21, y11, A22 * y21);
            float z22 = fmaf(A21, y12, A22 * y22);
            float zc1 = fmaf(C1, y11, fmaf(C2, y21, WC * yc1));
            float zc2 = fmaf(C1, y12, fmaf(C2, y22, WC * yc2));
            float zwc = WC * ywc;
            float s = __fdividef(1.0f, z22);
            A11 = z11 * s; A12 = z12 * s; A21 = z21 * s; A22 = z22 * s;
            C1 = zc1 * s;  C2 = zc2 * s;  WC = zwc * s;
        }
    }
    float E12 = __shfl_down_sync(0xffffffffu, A12, 1);
    float E22 = __shfl_down_sync(0xffffffffu, A22, 1);
    float Ec2 = __shfl_down_sync(0xffffffffu, C2,  1);
    if (k == 31) { E12 = 0.f; E22 = 1.f; Ec2 = 0.f; }
    float a  = E12 / E22;
    float ab = Ec2 / E22;

    // ---- backward replay, emitting forward coefficients directly ----
    // inv = 1/(1+l+a_pre); bet = (lm+ab_pre)*inv + sqrt(1-a_pre)*e;
    // ab_new = (lm+ab_pre)*inv (same product), a_new = (l+a_pre)*inv.
    float inv[CH], bet[CH];
#pragma unroll
    for (int v = 3; v >= 0; --v) {
        float4 e = reinterpret_cast<const float4*>(eps_ab + base)[v];
        float ev[4] = {e.x, e.y, e.z, e.w};
#pragma unroll
        for (int s = 3; s >= 0; --s) {
            int i = v*4 + s;
            if (l[i] >= 0.f) {
                float d   = l[i] + a;
                float iv  = __fdividef(1.0f, 1.0f + d);
                float nab = (lm[i] + ab) * iv;
                inv[i] = iv;
                bet[i] = fmaf(sqrtf(fmaxf(0.0f, 1.0f - a)), ev[s], nab);
                a  = d * iv;
                ab = nab;
            } else {
                inv[i] = 1.0f; bet[i] = 0.0f;
            }
        }
    }

    // ---- per-lane affine compose (t ascending) ----
    float alC = 1.f, beC = 0.f;
#pragma unroll
    for (int i = 0; i < CH; ++i) {
        beC = fmaf(inv[i], beC, bet[i]);
        alC *= inv[i];
    }

    // ---- warp prefix scan of affine pairs ----
#pragma unroll
    for (int off = 1; off < 32; off <<= 1) {
        float ya = __shfl_up_sync(0xffffffffu, alC, off);
        float yb = __shfl_up_sync(0xffffffffu, beC, off);
        if (k >= off) {
            beC = fmaf(alC, yb, beC);
            alC *= ya;
        }
    }
    float th = __shfl_up_sync(0xffffffffu, beC, 1);
    if (k == 0) th = 0.f;

    // ---- forward replay + streaming float4 outputs (q_id reloaded, L1) ----
#pragma unroll
    for (int g = 0; g < 4; ++g) {
        int4 q = reinterpret_cast<const int4*>(q_id + base)[g];
        int qv[4] = {q.x, q.y, q.z, q.w};
        float4 lof, aof;
#pragma unroll
        for (int s = 0; s < 4; ++s) {
            int i = 4*g + s;
            th = fmaf(th, inv[i], bet[i]);     // identity when masked
            float dc = g_disc[qv[s]];
            float lv = dc * (th - g_diff[qv[s]]);
            if (s == 0) { lof.x = lv; aof.x = th; }
            else if (s == 1) { lof.y = lv; aof.y = th; }
            else if (s == 2) { lof.z = lv; aof.z = th; }
            else { lof.w = lv; aof.w = th; }
        }
        reinterpret_cast<float4*>(out + base)[g] = lof;
        reinterpret_cast<float4*>(out + UT + base)[g] = aof;
    }
}

// ---------------------------------------------------------------------------
// Launch
// ---------------------------------------------------------------------------
extern "C" void kernel_launch(void* const* d_in, const int* in_sizes, int n_in,
                              void* d_out, int out_size) {
    const int*   mask   = (const int*)  d_in[0];
    const int*   q_id   = (const int*)  d_in[1];
    const float* resp   = (const float*)d_in[2];
    const float* dmu    = (const float*)d_in[3];
    const float* dlv    = (const float*)d_in[4];
    const float* cmu    = (const float*)d_in[5];
    const float* clv    = (const float*)d_in[6];
    const float* W1     = (const float*)d_in[7];
    const float* b1     = (const float*)d_in[8];
    const float* W2     = (const float*)d_in[9];
    const float* b2     = (const float*)d_in[10];
    const float* W3     = (const float*)d_in[11];
    const float* b3     = (const float*)d_in[12];
    const float* ed     = (const float*)d_in[13];
    const float* ec     = (const float*)d_in[14];
    const float* eps_ab = (const float*)d_in[15];
    float* out = (float*)d_out;

    table_kernel<<<TBLK, 256>>>(dmu, dlv, cmu, clv, ed, ec,
                                W1, b1, W2, b2, W3, b3);
    fused_scan_kernel<<<UU / 4, 128>>>(mask, q_id, resp, eps_ab, out);
}

// round 14
// speedup vs baseline: 1.0007x; 1.0007x over previous
#include <cuda_runtime.h>
#include <math.h>

// Problem shape (fixed by reference setup_inputs)
#define UU 2048
#define TT 512
#define QQ 10000
#define HH 128
#define UT (UU*TT)
#define CH2 8          // scan: time steps per lane (2 warps/user * 32 lanes * 8 = 512)

#define TBLK 592       // table kernel blocks (4/SM)
#define NCHUNK 1250    // 16-pair chunks: 1250*16 = 20000 exactly

// Scratch (device globals: allocation-free, graph-capturable)
__device__ float  g_diff[QQ];
__device__ float  g_disc[QQ];
__device__ float2 g_tab[2*QQ];     // (mu, lmda) per (q, resp)

__device__ __forceinline__ float gelu_exact(float x) {
    return 0.5f * x * (1.0f + erff(x * 0.70710678118654752440f));
}

// ---------------------------------------------------------------------------
// Kernel 1 (fused sample + MLP table): resp = round(uniform) in {0,1}, so the
// MLP has only 2*QQ distinct inputs. 256 threads/block, two 128-thread halves,
// each half computes 8 pairs (4 q x 2 resp) per W2 pass. Layer-2 uses TWO
// independent accumulator banks per pair (2-deep FMA chains, 16 chains of ILP).
// ---------------------------------------------------------------------------
__global__ void __launch_bounds__(256, 4) table_kernel(
        const float* __restrict__ dmu, const float* __restrict__ dlv,
        const float* __restrict__ cmu, const float* __restrict__ clv,
        const float* __restrict__ ed,  const float* __restrict__ ec,
        const float* __restrict__ W1, const float* __restrict__ b1,
        const float* __restrict__ W2, const float* __restrict__ b2,
        const float* __restrict__ W3, const float* __restrict__ b3) {
    const int tid  = threadIdx.x;
    const int half = tid >> 7;          // 0 or 1
    const int j    = tid & 127;         // channel
    const int wwarp = (tid >> 5) & 3;   // warp within half
    const int lane  = tid & 31;

    // ---- folded sample pass (first 40 blocks cover QQ) ----
    int gid = blockIdx.x * 256 + tid;
    if (gid < QQ) {
        g_diff[gid] = fmaf(__expf(0.5f * dlv[gid]), ed[gid], dmu[gid]);
        g_disc[gid] = fmaf(__expf(0.5f * clv[gid]), ec[gid], cmu[gid]);
    }

    __shared__ __align__(16) float h1s[16][HH];   // 16 pairs per chunk
    __shared__ float s_red[16][2][4];             // [pair][comp][warp]

    const float w1a = __ldg(&W1[j]);
    const float w1b = __ldg(&W1[HH + j]);
    const float w1c = __ldg(&W1[2*HH + j]);
    const float b1j = __ldg(&b1[j]);
    const float b2j = __ldg(&b2[j]);
    const float w3a = __ldg(&W3[2*j + 0]);
    const float w3b = __ldg(&W3[2*j + 1]);
    const float b30 = __ldg(&b3[0]);
    const float b31 = __ldg(&b3[1]);

    for (int c = blockIdx.x; c < NCHUNK; c += TBLK) {
        const int pbase = c * 16;            // 16 pairs; all < 2*QQ by range
        const int qbase = c * 8 + half * 4;  // this half's 4 q's

        // ---- layer 1: 4 q's x {resp=0,1} -> 8 h rows for this half ----
#pragma unroll
        for (int g = 0; g < 4; ++g) {
            int q = qbase + g;
            float td = fmaf(__expf(0.5f * __ldg(&dlv[q])), __ldg(&ed[q]), __ldg(&dmu[q]));
            float tc = fmaf(__expf(0.5f * __ldg(&clv[q])), __ldg(&ec[q]), __ldg(&cmu[q]));
            float pre0 = fmaf(td, w1a, fmaf(tc, w1b, b1j));   // resp = 0
            float pre1 = pre0 + w1c;                          // resp = 1
            h1s[half*8 + 2*g + 0][j] = gelu_exact(pre0);
            h1s[half*8 + 2*g + 1][j] = gelu_exact(pre1);
        }
        __syncthreads();

        // ---- layer 2: one W2 pass, 2 accumulator banks per pair ----
        float accA[8], accB[8];
#pragma unroll
        for (int p = 0; p < 8; ++p) { accA[p] = b2j; accB[p] = 0.f; }
#pragma unroll 4
        for (int kc = 0; kc < 32; ++kc) {
            int k = kc * 4;
            float w0 = __ldg(&W2[(k+0)*HH + j]);
            float w1 = __ldg(&W2[(k+1)*HH + j]);
            float w2 = __ldg(&W2[(k+2)*HH + j]);
            float w3 = __ldg(&W2[(k+3)*HH + j]);
#pragma unroll
            for (int p = 0; p < 8; ++p) {
                float4 v = *reinterpret_cast<const float4*>(&h1s[half*8 + p][k]);
                accA[p] = fmaf(v.x, w0, fmaf(v.z, w2, accA[p]));
                accB[p] = fmaf(v.y, w1, fmaf(v.w, w3, accB[p]));
            }
        }

        // ---- layer 3: 16 values per lane (8 pairs x {m0,m1}) ----
        float val[16];
#pragma unroll
        for (int p = 0; p < 8; ++p) {
            float hv = gelu_exact(accA[p] + accB[p]);
            val[2*p + 0] = hv * w3a;
            val[2*p + 1] = hv * w3b;
        }
        // Multi-value butterfly: stages o=16,8,4,2 halve the value count;
        // after them lane L owns value (L>>1)&15; stage o=1 finishes. 15 shfl.
        {
            bool b16 = (lane & 16) != 0;
#pragma unroll
            for (int i = 0; i < 8; ++i) {
                float send = b16 ? val[i] : val[8+i];
                float r = __shfl_xor_sync(0xffffffffu, send, 16);
                val[i] = (b16 ? val[8+i] : val[i]) + r;
            }
            bool b8 = (lane & 8) != 0;
#pragma unroll
            for (int i = 0; i < 4; ++i) {
                float send = b8 ? val[i] : val[4+i];
                float r = __shfl_xor_sync(0xffffffffu, send, 8);
                val[i] = (b8 ? val[4+i] : val[i]) + r;
            }
            bool b4 = (lane & 4) != 0;
#pragma unroll
            for (int i = 0; i < 2; ++i) {
                float send = b4 ? val[i] : val[2+i];
                float r = __shfl_xor_sync(0xffffffffu, send, 4);
                val[i] = (b4 ? val[2+i] : val[i]) + r;
            }
            bool b2v = (lane & 2) != 0;
            {
                float send = b2v ? val[0] : val[1];
                float r = __shfl_xor_sync(0xffffffffu, send, 2);
                val[0] = (b2v ? val[1] : val[0]) + r;
            }
            val[0] += __shfl_xor_sync(0xffffffffu, val[0], 1);
        }
        if ((lane & 1) == 0) {
            int v = (lane >> 1) & 15;       // owned value index: p*2 + comp
            s_red[half*8 + (v >> 1)][v & 1][wwarp] = val[0];
        }
        __syncthreads();

        if (tid < 16) {                     // one thread finalizes each pair
            int pair = pbase + tid;
            float mu = b30 + ((s_red[tid][0][0] + s_red[tid][0][1])
                            + (s_red[tid][0][2] + s_red[tid][0][3]));
            float p1 = b31 + ((s_red[tid][1][0] + s_red[tid][1][1])
                            + (s_red[tid][1][2] + s_red[tid][1][3]));
            g_tab[pair] = make_float2(mu, fminf(__expf(-p1), 1e32f));
        }
        __syncthreads();
    }
}

// ---------------------------------------------------------------------------
// Kernel 2 (fused): per-user scans with TWO warps per user (4096 warps total,
// occ ~43%). Warp w of user u covers t in [w*256, (w+1)*256); lane k owns
// CH2=8 steps. Cross-warp stitching through smem:
//  backward: upper warp's (w=1) lane-0 inclusive suffix = its half total T;
//            lower lanes compose full exclusive suffix E with T (Z = E*T).
//  forward:  lower warp's (w=0) lane-31 inclusive affine total (alT,beT);
//            upper lanes: th_in = al_excl*beT + be_excl.
// ---------------------------------------------------------------------------
__global__ void __launch_bounds__(256) fused_scan_kernel(
        const int*   __restrict__ mask,
        const int*   __restrict__ q_id,
        const float* __restrict__ resp,
        const float* __restrict__ eps_ab,
        float*       __restrict__ out) {
    const int tid = threadIdx.x;
    const int uu  = tid >> 6;            // user slot in block (0..3)
    const int u   = blockIdx.x * 4 + uu;
    const int w   = (tid >> 5) & 1;      // half index (0 = early t, 1 = late t)
    const int k   = tid & 31;
    const int base = u * TT + w * 256 + k * CH2;

    __shared__ float sT[4][7];   // upper-half backward total per user
    __shared__ float sF[4][2];   // lower-half forward total per user

    // ---- preprocess 8 trials -> l (sign-encoded mask), lm ----
    float l[CH2], lm[CH2];
#pragma unroll
    for (int v = 0; v < 2; ++v) {
        int4   mk = reinterpret_cast<const int4*>(mask + base)[v];
        int4   q  = reinterpret_cast<const int4*>(q_id + base)[v];
        float4 r  = reinterpret_cast<const float4*>(resp + base)[v];
        int   mkv[4] = {mk.x, mk.y, mk.z, mk.w};
        int   qv[4]  = {q.x, q.y, q.z, q.w};
        float rv[4]  = {r.x, r.y, r.z, r.w};
#pragma unroll
        for (int s = 0; s < 4; ++s) {
            int i = v*4 + s;
            float2 ml = g_tab[(qv[s] << 1) | (rv[s] > 0.5f ? 1 : 0)];
            bool m = (mkv[s] != 0);
            l[i]  = m ? ml.y : -1.0f;     // l >= 0 always when unmasked
            lm[i] = ml.y * ml.x;          // unused when masked
        }
    }

    // ---- backward: per-lane chunk matrix over CH2 steps ----
    float A11 = 1.f, A12 = 0.f, A21 = 0.f, A22 = 1.f;
    float C1 = 0.f, C2 = 0.f, WC = 1.f;
#pragma unroll
    for (int i = CH2 - 1; i >= 0; --i) {
        if (l[i] >= 0.f) {
            float li = l[i];
            float s  = __fdividef(1.0f, 1.0f + li);
            float n11 = (A11 + li * A21) * s;
            float n12 = (A12 + li * A22) * s;
            float n21 = n11 + A21 * s;
            float n22 = n12 + A22 * s;
            float nc1 = fmaf(lm[i], A21, C1) * s;
            float nc2 = fmaf(lm[i], A22, C2) * s;
            A11 = n11; A12 = n12; A21 = n21; A22 = n22;
            C1 = nc1; C2 = nc2; WC *= s;
        }
    }
    {
        float s = __fdividef(1.0f, A22);
        A11 *= s; A12 *= s; A21 *= s; A22 *= s;
        C1 *= s; C2 *= s; WC *= s;
    }

    // ---- warp suffix scan (Z = A*Y; w-row: zc = C*y + WC*yc) ----
#pragma unroll
    for (int off = 1; off < 32; off <<= 1) {
        float y11 = __shfl_down_sync(0xffffffffu, A11, off);
        float y12 = __shfl_down_sync(0xffffffffu, A12, off);
        float y21 = __shfl_down_sync(0xffffffffu, A21, off);
        float y22 = __shfl_down_sync(0xffffffffu, A22, off);
        float yc1 = __shfl_down_sync(0xffffffffu, C1,  off);
        float yc2 = __shfl_down_sync(0xffffffffu, C2,  off);
        float ywc = __shfl_down_sync(0xffffffffu, WC,  off);
        if (k + off < 32) {
            float z11 = fmaf(A11, y11, A12 * y21);
            float z12 = fmaf(A11, y12, A12 * y22);
            float z21 = fmaf(A21, y11, A22 * y21);
            float z22 = fmaf(A21, y12, A22 * y22);
            float zc1 = fmaf(C1, y11, fmaf(C2, y21, WC * yc1));
            float zc2 = fmaf(C1, y12, fmaf(C2, y22, WC * yc2));
            float zwc = WC * ywc;
            float s = __fdividef(1.0f, z22);
            A11 = z11 * s; A12 = z12 * s; A21 = z21 * s; A22 = z22 * s;
            C1 = zc1 * s;  C2 = zc2 * s;  WC = zwc * s;
        }
    }

    // upper warp's lane 0 now holds the total composite of the late half
    if (w == 1 && k == 0) {
        sT[uu][0] = A11; sT[uu][1] = A12; sT[uu][2] = A21; sT[uu][3] = A22;
        sT[uu][4] = C1;  sT[uu][5] = C2;  sT[uu][6] = WC;
    }

    // full exclusive suffix E per lane (identity at lane 31)
    float E11 = __shfl_down_sync(0xffffffffu, A11, 1);
    float E12 = __shfl_down_sync(0xffffffffu, A12, 1);
    float E21 = __shfl_down_sync(0xffffffffu, A21, 1);
    float E22 = __shfl_down_sync(0xffffffffu, A22, 1);
    float Ec1 = __shfl_down_sync(0xffffffffu, C1,  1);
    float Ec2 = __shfl_down_sync(0xffffffffu, C2,  1);
    float Ewc = __shfl_down_sync(0xffffffffu, WC,  1);
    if (k == 31) { E11 = 1.f; E12 = 0.f; E21 = 0.f; E22 = 1.f;
                   Ec1 = 0.f; Ec2 = 0.f; Ewc = 1.f; }
    __syncthreads();

    float a, ab;
    if (w == 0) {
        // compose Z = E * T (E newer/earlier-t, T = upper-half total)
        float t11 = sT[uu][0], t12 = sT[uu][1], t21 = sT[uu][2], t22 = sT[uu][3];
        float tc1 = sT[uu][4], tc2 = sT[uu][5];
        float z12 = fmaf(E11, t12, E12 * t22);
        float z22 = fmaf(E21, t12, E22 * t22);
        float zc2 = fmaf(Ec1, t12, fmaf(Ec2, t22, Ewc * tc2));
        a  = z12 / z22;
        ab = zc2 / z22;
        (void)t11; (void)t21; (void)tc1;
    } else {
        a  = E12 / E22;
        ab = Ec2 / E22;
    }

    // ---- backward replay, emitting forward coefficients directly ----
    // inv = 1/(1+l+a_pre); bet = (lm+ab_pre)*inv + sqrt(1-a_pre)*e;
    // ab_new = (lm+ab_pre)*inv, a_new = (l+a_pre)*inv.
    float inv[CH2], bet[CH2];
#pragma unroll
    for (int v = 1; v >= 0; --v) {
        float4 e = reinterpret_cast<const float4*>(eps_ab + base)[v];
        float ev[4] = {e.x, e.y, e.z, e.w};
#pragma unroll
        for (int s = 3; s >= 0; --s) {
            int i = v*4 + s;
            if (l[i] >= 0.f) {
                float d   = l[i] + a;
                float iv  = __fdividef(1.0f, 1.0f + d);
                float nab = (lm[i] + ab) * iv;
                inv[i] = iv;
                bet[i] = fmaf(sqrtf(fmaxf(0.0f, 1.0f - a)), ev[s], nab);
                a  = d * iv;
                ab = nab;
            } else {
                inv[i] = 1.0f; bet[i] = 0.0f;
            }
        }
    }

    // ---- per-lane affine compose (t ascending) ----
    float alC = 1.f, beC = 0.f;
#pragma unroll
    for (int i = 0; i < CH2; ++i) {
        beC = fmaf(inv[i], beC, bet[i]);
        alC *= inv[i];
    }

    // ---- warp inclusive prefix scan of affine pairs ----
#pragma unroll
    for (int off = 1; off < 32; off <<= 1) {
        float ya = __shfl_up_sync(0xffffffffu, alC, off);
        float yb = __shfl_up_sync(0xffffffffu, beC, off);
        if (k >= off) {
            beC = fmaf(alC, yb, beC);
            alC *= ya;
        }
    }

    // lower warp's lane 31 holds the early-half affine total
    if (w == 0 && k == 31) { sF[uu][0] = alC; sF[uu][1] = beC; }

    // exclusive prefix per lane
    float alE = __shfl_up_sync(0xffffffffu, alC, 1);
    float beE = __shfl_up_sync(0xffffffffu, beC, 1);
    if (k == 0) { alE = 1.f; beE = 0.f; }
    __syncthreads();

    float th;
    if (w == 1) {
        float beT = sF[uu][1];
        th = fmaf(alE, beT, beE);     // apply early-half total first (th0 = 0)
    } else {
        th = beE;
    }

    // ---- forward replay + streaming float4 outputs (q_id reloaded, L1) ----
#pragma unroll
    for (int g = 0; g < 2; ++g) {
        int4 q = reinterpret_cast<const int4*>(q_id + base)[g];
        int qv[4] = {q.x, q.y, q.z, q.w};
        float4 lof, aof;
#pragma unroll
        for (int s = 0; s < 4; ++s) {
            int i = 4*g + s;
            th = fmaf(th, inv[i], bet[i]);     // identity when masked
            float dc = g_disc[qv[s]];
            float lv = dc * (th - g_diff[qv[s]]);
            if (s == 0) { lof.x = lv; aof.x = th; }
            else if (s == 1) { lof.y = lv; aof.y = th; }
            else if (s == 2) { lof.z = lv; aof.z = th; }
            else { lof.w = lv; aof.w = th; }
        }
        reinterpret_cast<float4*>(out + base)[g] = lof;
        reinterpret_cast<float4*>(out + UT + base)[g] = aof;
    }
}

// ---------------------------------------------------------------------------
// Launch
// ---------------------------------------------------------------------------
extern "C" void kernel_launch(void* const* d_in, const int* in_sizes, int n_in,
                              void* d_out, int out_size) {
    const int*   mask   = (const int*)  d_in[0];
    const int*   q_id   = (const int*)  d_in[1];
    const float* resp   = (const float*)d_in[2];
    const float* dmu    = (const float*)d_in[3];
    const float* dlv    = (const float*)d_in[4];
    const float* cmu    = (const float*)d_in[5];
    const float* clv    = (const float*)d_in[6];
    const float* W1     = (const float*)d_in[7];
    const float* b1     = (const float*)d_in[8];
    const float* W2     = (const float*)d_in[9];
    const float* b2     = (const float*)d_in[10];
    const float* W3     = (const float*)d_in[11];
    const float* b3     = (const float*)d_in[12];
    const float* ed     = (const float*)d_in[13];
    const float* ec     = (const float*)d_in[14];
    const float* eps_ab = (const float*)d_in[15];
    float* out = (float*)d_out;

    table_kernel<<<TBLK, 256>>>(dmu, dlv, cmu, clv, ed, ec,
                                W1, b1, W2, b2, W3, b3);
    fused_scan_kernel<<<UU / 4, 256>>>(mask, q_id, resp, eps_ab, out);
}